// round 16
// baseline (speedup 1.0000x reference)
#include <cuda_runtime.h>
#include <math.h>

#define B_  2
#define S_  2048
#define D_  1024
#define H_  16
#define DK_ 64
#define BS_ (B_*S_)   // 4096

// ---------------- scratch ----------------
__device__ float g_Qh[B_*H_*S_*DK_];   // [B,H,S,DK]
__device__ float g_Kh[B_*H_*S_*DK_];
__device__ float g_Vh[B_*H_*S_*DK_];
__device__ float g_ctx[BS_*D_];        // concat [B,S,D]
__device__ float g_x[BS_*D_];          // pre-LN (full fp32)
__device__ int   g_mflag[B_*16*32];    // per (b, qtile128, ktile64): any mask zero?

// ---------------- helpers ----------------
__device__ __forceinline__ void mma8(float& c0, float& c1, float& c2, float& c3,
                                     unsigned a0, unsigned a1, unsigned a2, unsigned a3,
                                     unsigned b0, unsigned b1) {
    asm volatile(
        "mma.sync.aligned.m16n8k8.row.col.f32.tf32.tf32.f32 "
        "{%0,%1,%2,%3},{%4,%5,%6,%7},{%8,%9},{%0,%1,%2,%3};"
        : "+f"(c0), "+f"(c1), "+f"(c2), "+f"(c3)
        : "r"(a0), "r"(a1), "r"(a2), "r"(a3), "r"(b0), "r"(b1));
}

__device__ __forceinline__ void cpasync16(unsigned dst, const void* src) {
    asm volatile("cp.async.cg.shared.global [%0], [%1], 16;" :: "r"(dst), "l"(src));
}
#define CP_COMMIT() asm volatile("cp.async.commit_group;")
#define CP_WAIT1()  asm volatile("cp.async.wait_group 1;")
#define CP_WAIT0()  asm volatile("cp.async.wait_group 0;")

// ===========================================================================
// Mask summary: flag per (b, qtile 128, ktile 64) whether any zero present
// ===========================================================================
__global__ void maskflag_kernel(const int* __restrict__ mask)
{
    const int kt = blockIdx.x, qt = blockIdx.y, b = blockIdx.z;
    const int* mb = mask + ((size_t)b * S_ + qt * 128) * S_ + kt * 64;
    const int t = threadIdx.x;
    int anyz = 0;
#pragma unroll
    for (int i = 0; i < 8; i++) {
        int lin = t + 256 * i;
        int row = lin >> 4;
        int c4  = (lin & 15) * 4;
        int4 v = *(const int4*)(mb + (size_t)row * S_ + c4);
        anyz |= (v.x == 0) | (v.y == 0) | (v.z == 0) | (v.w == 0);
    }
    anyz = __syncthreads_or(anyz);
    if (t == 0) g_mflag[(b * 16 + qt) * 32 + kt] = anyz;
}

// ===========================================================================
// tf32 GEMM (raw fp32 operands; HW truncates), cp.async 3-stage ring,
// ONE barrier per k-iteration.  BM=BN=128, BK=32, 8 warps (64x32 each).
// mode 0: grid.z selects q/k/v; scatter C+bias to head layout
// mode 1: g_x = (g_ctx @ Wo^T) + bias + res (fp32)
// ===========================================================================
#define GAST 36
#define GEMM_STAGE_FLOATS (128*GAST*2)       // 9216
#define GEMM_SMEM (3*GEMM_STAGE_FLOATS*4)    // 110592 bytes

__global__ __launch_bounds__(256) void gemm_tc(const float* __restrict__ x0,
                                               const float* __restrict__ x1,
                                               const float* __restrict__ x2,
                                               const float* __restrict__ w0,
                                               const float* __restrict__ w1,
                                               const float* __restrict__ w2,
                                               const float* __restrict__ bias0,
                                               const float* __restrict__ bias1,
                                               const float* __restrict__ bias2,
                                               const float* __restrict__ res,
                                               int mode)
{
    extern __shared__ float gsm[];

    const int which = (mode == 1) ? 0 : blockIdx.z;
    const float* bias = (which == 0) ? bias0 : (which == 1) ? bias1 : bias2;
    const float* X = (mode == 1) ? (const float*)g_ctx
                                 : (which == 0) ? x0 : (which == 1) ? x1 : x2;
    const float* W = (which == 0) ? w0 : (which == 1) ? w1 : w2;
    float* outp = (which == 0) ? g_Qh : (which == 1) ? g_Kh : g_Vh;

    const int bm = blockIdx.y * 128;
    const int bn = blockIdx.x * 128;
    const int t    = threadIdx.x;
    const int w    = t >> 5;
    const int lane = t & 31;
    const int gid  = lane >> 2;
    const int tid  = lane & 3;
    const int wm   = (w & 1) * 64;
    const int wn   = (w >> 1) * 32;

    const unsigned smaddr = (unsigned)__cvta_generic_to_shared(gsm);

    float c[4][4][4];
#pragma unroll
    for (int i = 0; i < 4; i++)
#pragma unroll
        for (int j = 0; j < 4; j++)
#pragma unroll
            for (int r = 0; r < 4; r++) c[i][j][r] = 0.f;

    // prologue: prefetch stages 0 and 1
#pragma unroll
    for (int pt = 0; pt < 2; pt++) {
        unsigned ab = smaddr + pt * GEMM_STAGE_FLOATS * 4;
        unsigned bb = ab + 128 * GAST * 4;
        const int k0p = pt * 32;
#pragma unroll
        for (int i = 0; i < 4; i++) {
            int idx = t + 256 * i;
            int row = idx >> 3;
            int c4  = (idx & 7) << 2;
            cpasync16(ab + (row * GAST + c4) * 4, X + (size_t)(bm + row) * D_ + k0p + c4);
            cpasync16(bb + (row * GAST + c4) * 4, W + (size_t)(bn + row) * D_ + k0p + c4);
        }
        CP_COMMIT();
    }

    const int NI = D_ / 32;   // 32
    for (int it = 0; it < NI; it++) {
        const int cur = it % 3;
        if (it < NI - 1) { CP_WAIT1(); } else { CP_WAIT0(); }
        __syncthreads();   // stage cur visible to all; all done with iter it-1

        if (it + 2 < NI) {
            const int nstage = (it + 2) % 3;
            const int k0n = (it + 2) * 32;
            unsigned ab = smaddr + nstage * GEMM_STAGE_FLOATS * 4;
            unsigned bb = ab + 128 * GAST * 4;
#pragma unroll
            for (int i = 0; i < 4; i++) {
                int idx = t + 256 * i;
                int row = idx >> 3;
                int c4  = (idx & 7) << 2;
                cpasync16(ab + (row * GAST + c4) * 4, X + (size_t)(bm + row) * D_ + k0n + c4);
                cpasync16(bb + (row * GAST + c4) * 4, W + (size_t)(bn + row) * D_ + k0n + c4);
            }
            CP_COMMIT();
        }

        const float* Ab = gsm + cur * GEMM_STAGE_FLOATS;
        const float* Bb = Ab + 128 * GAST;

#pragma unroll
        for (int ks = 0; ks < 4; ks++) {
            const int k = ks * 8;
            unsigned a0[4], a1[4], a2[4], a3[4], bf0[4], bf1[4];
#pragma unroll
            for (int i = 0; i < 4; i++) {
                int r0 = wm + i * 16 + gid;
                a0[i] = __float_as_uint(Ab[(r0    ) * GAST + k + tid]);
                a1[i] = __float_as_uint(Ab[(r0 + 8) * GAST + k + tid]);
                a2[i] = __float_as_uint(Ab[(r0    ) * GAST + k + tid + 4]);
                a3[i] = __float_as_uint(Ab[(r0 + 8) * GAST + k + tid + 4]);
            }
#pragma unroll
            for (int j = 0; j < 4; j++) {
                int n0 = wn + j * 8 + gid;
                bf0[j] = __float_as_uint(Bb[n0 * GAST + k + tid]);
                bf1[j] = __float_as_uint(Bb[n0 * GAST + k + tid + 4]);
            }
#pragma unroll
            for (int i = 0; i < 4; i++)
#pragma unroll
                for (int j = 0; j < 4; j++)
                    mma8(c[i][j][0], c[i][j][1], c[i][j][2], c[i][j][3],
                         a0[i], a1[i], a2[i], a3[i], bf0[j], bf1[j]);
        }
    }

#pragma unroll
    for (int i = 0; i < 4; i++) {
        int r0 = bm + wm + i * 16 + gid;
        int r1 = r0 + 8;
#pragma unroll
        for (int j = 0; j < 4; j++) {
            int n0 = bn + wn + j * 8 + tid * 2;
            int n1 = n0 + 1;
            if (mode == 0) {
                int b0i = r0 >> 11, s0 = r0 & (S_ - 1);
                int b1i = r1 >> 11, s1 = r1 & (S_ - 1);
                int h0 = n0 >> 6, d0 = n0 & 63;
                int h1 = n1 >> 6, d1 = n1 & 63;
                outp[(((size_t)(b0i * H_ + h0)) * S_ + s0) * DK_ + d0] = c[i][j][0] + bias[n0];
                outp[(((size_t)(b0i * H_ + h1)) * S_ + s0) * DK_ + d1] = c[i][j][1] + bias[n1];
                outp[(((size_t)(b1i * H_ + h0)) * S_ + s1) * DK_ + d0] = c[i][j][2] + bias[n0];
                outp[(((size_t)(b1i * H_ + h1)) * S_ + s1) * DK_ + d1] = c[i][j][3] + bias[n1];
            } else {
                g_x[(size_t)r0 * D_ + n0] = c[i][j][0] + bias[n0] + res[(size_t)r0 * D_ + n0];
                g_x[(size_t)r0 * D_ + n1] = c[i][j][1] + bias[n1] + res[(size_t)r0 * D_ + n1];
                g_x[(size_t)r1 * D_ + n0] = c[i][j][2] + bias[n0] + res[(size_t)r1 * D_ + n0];
                g_x[(size_t)r1 * D_ + n1] = c[i][j][3] + bias[n1] + res[(size_t)r1 * D_ + n1];
            }
        }
    }
}

// ===========================================================================
// Flash attention, tf32 mma. Q frags in registers, P in registers via quad
// shuffles, 3-stage cp.async K/V ring, ONE barrier per tile.
// Bq=128 (8 warps x 16 rows), Bk=64.
// smem: Ks[3][64][68] + Vs[3][64][72] = 26880 floats -> 2 blocks/SM
// ===========================================================================
#define QST 68
#define VST 72
#define F_KS   0
#define F_VS   (3*64*QST)
#define FLASH_FLOATS (F_VS + 3*64*VST)   // 26880
#define FLASH_SMEM   (FLASH_FLOATS*4)    // 107520 B

__global__ __launch_bounds__(256, 2) void flash_tc(const int* __restrict__ mask)
{
    extern __shared__ float sm[];

    const int b  = blockIdx.z;
    const int h  = blockIdx.y;
    const int q0 = blockIdx.x * 128;
    const int t    = threadIdx.x;
    const int w    = t >> 5;
    const int lane = t & 31;
    const int gid  = lane >> 2;
    const int tid  = lane & 3;

    const float* Qg = g_Qh + ((size_t)(b * H_ + h)) * S_ * DK_;
    const float* Kg = g_Kh + ((size_t)(b * H_ + h)) * S_ * DK_;
    const float* Vg = g_Vh + ((size_t)(b * H_ + h)) * S_ * DK_;
    const int* mbase = mask + (size_t)b * S_ * S_;
    const int* mflag = g_mflag + (b * 16 + blockIdx.x) * 32;

    const unsigned smaddr = (unsigned)__cvta_generic_to_shared(sm);
    const int rloc0 = w * 16 + gid;
    const int rloc1 = rloc0 + 8;

    // ---- stage Q through Ks[0..1], pull frags to registers ----
    {
        float* Qs = sm + F_KS;
#pragma unroll
        for (int i = 0; i < 8; i++) {
            int l4  = t + 256 * i;
            int row = l4 >> 4;
            int dg  = (l4 & 15) << 2;
            *(float4*)(Qs + row * QST + dg) =
                *(const float4*)(Qg + (size_t)(q0 + row) * DK_ + dg);
        }
        __syncthreads();
    }
    unsigned qr[32];
    {
        const float* Qs = sm + F_KS;
#pragma unroll
        for (int kk = 0; kk < 8; kk++) {
            const int k = kk * 8;
            qr[kk * 4 + 0] = __float_as_uint(Qs[rloc0 * QST + k + tid]);
            qr[kk * 4 + 1] = __float_as_uint(Qs[rloc1 * QST + k + tid]);
            qr[kk * 4 + 2] = __float_as_uint(Qs[rloc0 * QST + k + tid + 4]);
            qr[kk * 4 + 3] = __float_as_uint(Qs[rloc1 * QST + k + tid + 4]);
        }
    }
    __syncthreads();   // Q read by all; safe to overwrite with K prefetch

    // ---- prefetch K/V tiles 0 and 1 ----
#pragma unroll
    for (int pt = 0; pt < 2; pt++) {
        unsigned ka = smaddr + (F_KS + pt * 64 * QST) * 4;
        unsigned va = smaddr + (F_VS + pt * 64 * VST) * 4;
        const int k0p = pt * 64;
#pragma unroll
        for (int i = 0; i < 4; i++) {
            int l4  = t + 256 * i;
            int row = l4 >> 4;
            int dg  = (l4 & 15) << 2;
            cpasync16(ka + (row * QST + dg) * 4, Kg + (size_t)(k0p + row) * DK_ + dg);
            cpasync16(va + (row * VST + dg) * 4, Vg + (size_t)(k0p + row) * DK_ + dg);
        }
        CP_COMMIT();
    }

    float o[8][4];
#pragma unroll
    for (int j = 0; j < 8; j++)
#pragma unroll
        for (int r = 0; r < 4; r++) o[j][r] = 0.f;
    float mprev0 = -1e30f, mprev1 = -1e30f, lsum0 = 0.f, lsum1 = 0.f;

    const int NT = S_ / 64;
    for (int kt = 0; kt < NT; kt++) {
        const int cur = kt % 3;
        if (kt < NT - 1) { CP_WAIT1(); } else { CP_WAIT0(); }
        __syncthreads();   // stage cur visible; all done with tile kt-1

        if (kt + 2 < NT) {
            const int nstage = (kt + 2) % 3;
            const int k0n = (kt + 2) * 64;
            unsigned ka = smaddr + (F_KS + nstage * 64 * QST) * 4;
            unsigned va = smaddr + (F_VS + nstage * 64 * VST) * 4;
#pragma unroll
            for (int i = 0; i < 4; i++) {
                int l4  = t + 256 * i;
                int row = l4 >> 4;
                int dg  = (l4 & 15) << 2;
                cpasync16(ka + (row * QST + dg) * 4, Kg + (size_t)(k0n + row) * DK_ + dg);
                cpasync16(va + (row * VST + dg) * 4, Vg + (size_t)(k0n + row) * DK_ + dg);
            }
            CP_COMMIT();
        }

        const float* Ks = sm + F_KS + cur * 64 * QST;
        const float* Vs = sm + F_VS + cur * 64 * VST;
        const int k0 = kt * 64;

        // ---- S = Q @ K^T (Q from registers) ----
        float s[8][4];
#pragma unroll
        for (int j = 0; j < 8; j++)
#pragma unroll
            for (int r = 0; r < 4; r++) s[j][r] = 0.f;

#pragma unroll
        for (int kk = 0; kk < 8; kk++) {
            const int k = kk * 8;
            const unsigned qa0 = qr[kk * 4 + 0];
            const unsigned qa1 = qr[kk * 4 + 1];
            const unsigned qa2 = qr[kk * 4 + 2];
            const unsigned qa3 = qr[kk * 4 + 3];
#pragma unroll
            for (int j = 0; j < 8; j++) {
                unsigned b0 = __float_as_uint(Ks[(j * 8 + gid) * QST + k + tid]);
                unsigned b1 = __float_as_uint(Ks[(j * 8 + gid) * QST + k + tid + 4]);
                mma8(s[j][0], s[j][1], s[j][2], s[j][3], qa0, qa1, qa2, qa3, b0, b1);
            }
        }

        // ---- scale (+mask only if tile has zeros) ----
        const float scale = 0.125f;
#pragma unroll
        for (int j = 0; j < 8; j++) {
            s[j][0] *= scale; s[j][1] *= scale;
            s[j][2] *= scale; s[j][3] *= scale;
        }
        if (mflag[kt]) {
            const int gr0 = q0 + rloc0;
            const int gr1 = q0 + rloc1;
#pragma unroll
            for (int j = 0; j < 8; j++) {
                int col = k0 + j * 8 + tid * 2;
                const int* m0p = mbase + (size_t)gr0 * S_ + col;
                const int* m1p = mbase + (size_t)gr1 * S_ + col;
                if (m0p[0] == 0) s[j][0] = -1e9f;
                if (m0p[1] == 0) s[j][1] = -1e9f;
                if (m1p[0] == 0) s[j][2] = -1e9f;
                if (m1p[1] == 0) s[j][3] = -1e9f;
            }
        }

        // ---- online softmax (P stays in registers) ----
        float mx0 = -1e30f, mx1 = -1e30f;
#pragma unroll
        for (int j = 0; j < 8; j++) {
            mx0 = fmaxf(mx0, fmaxf(s[j][0], s[j][1]));
            mx1 = fmaxf(mx1, fmaxf(s[j][2], s[j][3]));
        }
#pragma unroll
        for (int off = 1; off <= 2; off <<= 1) {
            mx0 = fmaxf(mx0, __shfl_xor_sync(0xffffffffu, mx0, off));
            mx1 = fmaxf(mx1, __shfl_xor_sync(0xffffffffu, mx1, off));
        }
        float mn0 = fmaxf(mprev0, mx0);
        float mn1 = fmaxf(mprev1, mx1);
        float f0 = __expf(mprev0 - mn0);
        float f1 = __expf(mprev1 - mn1);
        float rs0 = 0.f, rs1 = 0.f;
#pragma unroll
        for (int j = 0; j < 8; j++) {
            s[j][0] = __expf(s[j][0] - mn0);
            s[j][1] = __expf(s[j][1] - mn0);
            s[j][2] = __expf(s[j][2] - mn1);
            s[j][3] = __expf(s[j][3] - mn1);
            rs0 += s[j][0] + s[j][1];
            rs1 += s[j][2] + s[j][3];
        }
#pragma unroll
        for (int off = 1; off <= 2; off <<= 1) {
            rs0 += __shfl_xor_sync(0xffffffffu, rs0, off);
            rs1 += __shfl_xor_sync(0xffffffffu, rs1, off);
        }
        lsum0 = lsum0 * f0 + rs0;
        lsum1 = lsum1 * f1 + rs1;
        mprev0 = mn0;
        mprev1 = mn1;
#pragma unroll
        for (int j = 0; j < 8; j++) {
            o[j][0] *= f0; o[j][1] *= f0;
            o[j][2] *= f1; o[j][3] *= f1;
        }

        // ---- O += P @ V : P A-frags from s[] via quad shuffles ----
        {
            const int e   = tid & 1;
            const int so  = tid >> 1;
            const int so2 = so + 2;
#pragma unroll
            for (int kk = 0; kk < 8; kk++) {
                const int k = kk * 8;
                float x0 = __shfl_sync(0xffffffffu, s[kk][0], so,  4);
                float x1 = __shfl_sync(0xffffffffu, s[kk][1], so,  4);
                float x2 = __shfl_sync(0xffffffffu, s[kk][2], so,  4);
                float x3 = __shfl_sync(0xffffffffu, s[kk][3], so,  4);
                float y0 = __shfl_sync(0xffffffffu, s[kk][0], so2, 4);
                float y1 = __shfl_sync(0xffffffffu, s[kk][1], so2, 4);
                float y2 = __shfl_sync(0xffffffffu, s[kk][2], so2, 4);
                float y3 = __shfl_sync(0xffffffffu, s[kk][3], so2, 4);
                unsigned pa0 = __float_as_uint(e ? x1 : x0);
                unsigned pa1 = __float_as_uint(e ? x3 : x2);
                unsigned pa2 = __float_as_uint(e ? y1 : y0);
                unsigned pa3 = __float_as_uint(e ? y3 : y2);
#pragma unroll
                for (int j = 0; j < 8; j++) {
                    unsigned b0 = __float_as_uint(Vs[(k + tid)     * VST + j * 8 + gid]);
                    unsigned b1 = __float_as_uint(Vs[(k + tid + 4) * VST + j * 8 + gid]);
                    mma8(o[j][0], o[j][1], o[j][2], o[j][3], pa0, pa1, pa2, pa3, b0, b1);
                }
            }
        }
    }

    // epilogue -> g_ctx
    float inv0 = 1.0f / lsum0;
    float inv1 = 1.0f / lsum1;
    float* out0 = g_ctx + ((size_t)b * S_ + (q0 + rloc0)) * D_ + h * DK_;
    float* out1 = g_ctx + ((size_t)b * S_ + (q0 + rloc1)) * D_ + h * DK_;
#pragma unroll
    for (int j = 0; j < 8; j++) {
        int col = j * 8 + tid * 2;
        out0[col + 0] = o[j][0] * inv0;
        out0[col + 1] = o[j][1] * inv0;
        out1[col + 0] = o[j][2] * inv1;
        out1[col + 1] = o[j][3] * inv1;
    }
}

// ===========================================================================
// LayerNorm over D=1024 per row
// ===========================================================================
__global__ __launch_bounds__(256) void ln_kernel(const float* __restrict__ gamma,
                                                 const float* __restrict__ beta,
                                                 float* __restrict__ out)
{
    const int row = blockIdx.x;
    const int t   = threadIdx.x;
    const float* x = g_x + (size_t)row * D_;

    float4 v = *(const float4*)(x + t * 4);
    float s  = v.x + v.y + v.z + v.w;
    float ss = v.x * v.x + v.y * v.y + v.z * v.z + v.w * v.w;
#pragma unroll
    for (int off = 16; off >= 1; off >>= 1) {
        s  += __shfl_xor_sync(0xffffffffu, s,  off);
        ss += __shfl_xor_sync(0xffffffffu, ss, off);
    }
    __shared__ float red[8][2];
    int w = t >> 5, ln = t & 31;
    if (ln == 0) { red[w][0] = s; red[w][1] = ss; }
    __syncthreads();
    s = 0.f; ss = 0.f;
#pragma unroll
    for (int i = 0; i < 8; i++) { s += red[i][0]; ss += red[i][1]; }

    float mean = s * (1.0f / D_);
    float var  = ss * (1.0f / D_) - mean * mean;
    float rstd = rsqrtf(var + 1e-5f);

    float4 g  = *(const float4*)(gamma + t * 4);
    float4 be = *(const float4*)(beta + t * 4);
    float4 ov;
    ov.x = (v.x - mean) * rstd * g.x + be.x;
    ov.y = (v.y - mean) * rstd * g.y + be.y;
    ov.z = (v.z - mean) * rstd * g.z + be.z;
    ov.w = (v.w - mean) * rstd * g.w + be.w;
    *(float4*)(out + (size_t)row * D_ + t * 4) = ov;
}

// ===========================================================================
extern "C" void kernel_launch(void* const* d_in, const int* in_sizes, int n_in,
                              void* d_out, int out_size)
{
    const float* q     = (const float*)d_in[0];
    const float* k     = (const float*)d_in[1];
    const float* v     = (const float*)d_in[2];
    const int*   mask  = (const int*)  d_in[3];
    const float* Wq    = (const float*)d_in[4];
    const float* bq    = (const float*)d_in[5];
    const float* Wk    = (const float*)d_in[6];
    const float* bk    = (const float*)d_in[7];
    const float* Wv    = (const float*)d_in[8];
    const float* bv    = (const float*)d_in[9];
    const float* Wo    = (const float*)d_in[10];
    const float* bo    = (const float*)d_in[11];
    const float* gamma = (const float*)d_in[12];
    const float* beta  = (const float*)d_in[13];
    float* out = (float*)d_out;

    maskflag_kernel<<<dim3(32, 16, B_), 256>>>(mask);

    cudaFuncSetAttribute(gemm_tc, cudaFuncAttributeMaxDynamicSharedMemorySize, GEMM_SMEM);
    gemm_tc<<<dim3(D_ / 128, BS_ / 128, 3), 256, GEMM_SMEM>>>(
        q, k, v, Wq, Wk, Wv, bq, bk, bv, nullptr, 0);

    cudaFuncSetAttribute(flash_tc, cudaFuncAttributeMaxDynamicSharedMemorySize, FLASH_SMEM);
    flash_tc<<<dim3(S_ / 128, H_, B_), 256, FLASH_SMEM>>>(mask);

    gemm_tc<<<dim3(D_ / 128, BS_ / 128, 1), 256, GEMM_SMEM>>>(
        nullptr, nullptr, nullptr, Wo, nullptr, nullptr, bo, nullptr, nullptr, q, 1);

    ln_kernel<<<BS_, 256>>>(gamma, beta, out);
}